// round 12
// baseline (speedup 1.0000x reference)
#include <cuda_runtime.h>
#include <math.h>
#include <stdint.h>

#define BB 2
#define SS 1024
#define DM 1024
#define NH 16
#define HD 64
#define FFD 4096
#define NL 12
#define RH 128
#define MM (BB*SS)    /* 2048 rows */
#define NZ (BB*NH)    /* 32 (b,h) batches */
#define VOC 32000

// ---------------- scratch (device globals: allocation-free contract) ----------------
__device__ float g_h  [MM*DM];   // plain residual + hi/lo planes (GEMM A operand)
__device__ float g_hh [MM*DM];
__device__ float g_hl [MM*DM];
__device__ float g_h1 [MM*DM];
__device__ float g_h1h[MM*DM];
__device__ float g_h1l[MM*DM];
__device__ float g_q  [MM*DM];
__device__ float g_k  [MM*DM];
__device__ float g_v  [MM*DM];
__device__ float g_atth[MM*DM];
__device__ float g_attl[MM*DM];
__device__ float g_ffh[MM*FFD];
__device__ float g_ffl[MM*FFD];
__device__ float g_t2 [MM*DM];
__device__ float g_rh [MM*RH];
__device__ float g_scores[(size_t)NZ*SS*SS];   // 128 MB
__device__ int   g_skip[MM];
__device__ int   g_cnt[3];
// tf32-split weight planes, native [K][N] layout (mma B wants K-major rows)
__device__ float g_wq_h[DM*DM],  g_wq_l[DM*DM];
__device__ float g_wk_h[DM*DM],  g_wk_l[DM*DM];
__device__ float g_wv_h[DM*DM],  g_wv_l[DM*DM];
__device__ float g_wo_h[DM*DM],  g_wo_l[DM*DM];
__device__ float g_wf1_h[(size_t)FFD*DM], g_wf1_l[(size_t)FFD*DM];
__device__ float g_wf2_h[(size_t)FFD*DM], g_wf2_l[(size_t)FFD*DM];
__device__ float g_wout_h[(size_t)VOC*DM], g_wout_l[(size_t)VOC*DM];
__device__ float g_rw1_h[NL*DM*RH], g_rw1_l[NL*DM*RH];

// ---------------- helpers ----------------
__device__ __forceinline__ unsigned f2tf(float f) {
    unsigned r; asm("cvt.rna.tf32.f32 %0, %1;" : "=r"(r) : "f"(f)); return r;
}
__device__ __forceinline__ void split2(float v, float& h, float& l) {
    h = __uint_as_float(f2tf(v));
    l = __uint_as_float(f2tf(v - h));
}
__device__ __forceinline__ void mma_tf32(float* d, const unsigned* a, const unsigned* b) {
    asm("mma.sync.aligned.m16n8k8.row.col.f32.tf32.tf32.f32 "
        "{%0,%1,%2,%3},{%4,%5,%6,%7},{%8,%9},{%0,%1,%2,%3};"
        : "+f"(d[0]), "+f"(d[1]), "+f"(d[2]), "+f"(d[3])
        : "r"(a[0]), "r"(a[1]), "r"(a[2]), "r"(a[3]), "r"(b[0]), "r"(b[1]));
}

// =====================================================================
// tf32x3 tensor-core GEMM with PRE-SPLIT operand planes.
// BM=128, BN=64, BK=16, 256 threads (8 warps, warp tile 32x32).
// SINGLE static smem buffer (26KB, no cudaFuncSetAttribute needed):
//   AH @0 (16x136), AL @2176, BH @4352 (16x72), BL @5504.
// Register prefetch hides gmem latency: LDG(next) -> MMA(cur) -> sync -> STS -> sync.
// Inner loop: LDS + HMMA only (zero conversions).  Strides 136/72 (== 8 mod 32)
// make all fragment gathers bank-conflict-free.
// =====================================================================
#define ABUF_OFF 2176
#define BH_OFF   4352
#define BL_OFF   5504
#define SM_FLOATS 6656   /* 26624 bytes static shared */

#define LDG_TILES(KK)                                                              \
    ah0 = *(const float4*)(Ahp + (size_t)aRow*K + (KK) + aCol);                    \
    ah1 = *(const float4*)(Ahp + (size_t)(aRow+64)*K + (KK) + aCol);               \
    al0 = *(const float4*)(Alp + (size_t)aRow*K + (KK) + aCol);                    \
    al1 = *(const float4*)(Alp + (size_t)(aRow+64)*K + (KK) + aCol);               \
    bh0 = *(const float4*)(Bhp + (size_t)((KK)+bRow)*N + bCol);                    \
    bl0 = *(const float4*)(Blp + (size_t)((KK)+bRow)*N + bCol);

#define STS_TILES()                                                                \
    {                                                                              \
        sm[(aCol+0)*136+aRow   ]=ah0.x; sm[(aCol+1)*136+aRow   ]=ah0.y;            \
        sm[(aCol+2)*136+aRow   ]=ah0.z; sm[(aCol+3)*136+aRow   ]=ah0.w;            \
        sm[(aCol+0)*136+aRow+64]=ah1.x; sm[(aCol+1)*136+aRow+64]=ah1.y;            \
        sm[(aCol+2)*136+aRow+64]=ah1.z; sm[(aCol+3)*136+aRow+64]=ah1.w;            \
        float* _bl = sm + ABUF_OFF;                                                \
        _bl[(aCol+0)*136+aRow   ]=al0.x; _bl[(aCol+1)*136+aRow   ]=al0.y;          \
        _bl[(aCol+2)*136+aRow   ]=al0.z; _bl[(aCol+3)*136+aRow   ]=al0.w;          \
        _bl[(aCol+0)*136+aRow+64]=al1.x; _bl[(aCol+1)*136+aRow+64]=al1.y;          \
        _bl[(aCol+2)*136+aRow+64]=al1.z; _bl[(aCol+3)*136+aRow+64]=al1.w;          \
        *(float4*)&sm[BH_OFF + bRow*72 + bCol] = bh0;                              \
        *(float4*)&sm[BL_OFF + bRow*72 + bCol] = bl0;                              \
    }

#define MMA_STAGE()                                                                \
  {                                                                                \
    _Pragma("unroll")                                                              \
    for (int kh = 0; kh < 2; kh++) {                                               \
      const int k0 = kh*8;                                                         \
      unsigned ahi[2][4], alo[2][4];                                               \
      _Pragma("unroll")                                                            \
      for (int mt = 0; mt < 2; mt++) {                                             \
        _Pragma("unroll")                                                          \
        for (int i = 0; i < 4; i++) {                                              \
          int rr = wm + mt*16 + (lane>>2) + ((i&1)<<3);                            \
          int kc = k0 + (lane&3) + ((i>>1)<<2);                                    \
          ahi[mt][i] = __float_as_uint(sm[kc*136 + rr]);                           \
          alo[mt][i] = __float_as_uint(sm[ABUF_OFF + kc*136 + rr]);                \
        }                                                                          \
      }                                                                            \
      _Pragma("unroll")                                                            \
      for (int nt = 0; nt < 4; nt++) {                                             \
        unsigned bhi[2], blo[2];                                                   \
        _Pragma("unroll")                                                          \
        for (int i = 0; i < 2; i++) {                                              \
          int kc = k0 + (lane&3) + (i<<2);                                         \
          int cc = wn + nt*8 + (lane>>2);                                          \
          bhi[i] = __float_as_uint(sm[BH_OFF + kc*72 + cc]);                       \
          blo[i] = __float_as_uint(sm[BL_OFF + kc*72 + cc]);                       \
        }                                                                          \
        _Pragma("unroll")                                                          \
        for (int mt = 0; mt < 2; mt++) {                                           \
          mma_tf32(acc[mt][nt], ahi[mt], bhi);                                     \
          mma_tf32(acc[mt][nt], alo[mt], bhi);                                     \
          mma_tf32(acc[mt][nt], ahi[mt], blo);                                     \
        }                                                                          \
      }                                                                            \
    }                                                                              \
  }

#define MMA_MAINLOOP()                                                             \
    float4 ah0, ah1, al0, al1, bh0, bl0;                                           \
    LDG_TILES(0)                                                                   \
    STS_TILES()                                                                    \
    __syncthreads();                                                               \
    for (int kk = 16; kk < K; kk += 16) {                                          \
        LDG_TILES(kk)                                                              \
        MMA_STAGE()                                                                \
        __syncthreads();                                                           \
        STS_TILES()                                                                \
        __syncthreads();                                                           \
    }                                                                              \
    MMA_STAGE()

// MODE 0: plain store.  MODE 1: relu, plain store.  MODE 2: relu, split store.
template<int MODE>
__global__ __launch_bounds__(256, 2) void k_gemm(const float* __restrict__ Ahp,
        const float* __restrict__ Alp, const float* __restrict__ Bhp,
        const float* __restrict__ Blp, const float* __restrict__ bias,
        float* __restrict__ C, float* __restrict__ C2, int N, int K) {
    __shared__ float sm[SM_FLOATS];
    int tid = threadIdx.x, lane = tid & 31, wid = tid >> 5;
    int wm = (wid & 3) * 32, wn = (wid >> 2) * 32;
    int aRow = tid >> 2, aCol = (tid & 3) << 2;
    int bRow = tid >> 4, bCol = (tid & 15) << 2;
    Ahp += (size_t)(blockIdx.y * 128) * K;
    Alp += (size_t)(blockIdx.y * 128) * K;
    Bhp += (size_t)blockIdx.x * 64;
    Blp += (size_t)blockIdx.x * 64;
    float acc[2][4][4] = {};

    MMA_MAINLOOP()

    int mBase = blockIdx.y*128 + wm + (lane>>2);
    int nBase = blockIdx.x*64  + wn + ((lane&3)<<1);
    #pragma unroll
    for (int mt = 0; mt < 2; mt++) {
        #pragma unroll
        for (int nt = 0; nt < 4; nt++) {
            int r = mBase + mt*16;
            int c = nBase + nt*8;
            float v0 = acc[mt][nt][0] + bias[c];
            float v1 = acc[mt][nt][1] + bias[c+1];
            float v2 = acc[mt][nt][2] + bias[c];
            float v3 = acc[mt][nt][3] + bias[c+1];
            if (MODE >= 1) {
                v0 = fmaxf(v0,0.f); v1 = fmaxf(v1,0.f);
                v2 = fmaxf(v2,0.f); v3 = fmaxf(v3,0.f);
            }
            float* p  = C + (size_t)r*N + c;
            float* p2 = p + (size_t)8*N;
            if (MODE == 2) {
                float h, l;
                float* q  = C2 + (size_t)r*N + c;
                float* q2 = q + (size_t)8*N;
                split2(v0,h,l); p [0]=h; q [0]=l;
                split2(v1,h,l); p [1]=h; q [1]=l;
                split2(v2,h,l); p2[0]=h; q2[0]=l;
                split2(v3,h,l); p2[1]=h; q2[1]=l;
            } else {
                p [0] = v0; p [1] = v1;
                p2[0] = v2; p2[1] = v3;
            }
        }
    }
}

// fused QKV: grid.x in [0,48): sel = bx>>4 picks W/bias/output, head = bx&15.
__global__ __launch_bounds__(256, 2) void k_gemm_qkv(const float* __restrict__ Ahp,
        const float* __restrict__ Alp,
        const float* __restrict__ bq, const float* __restrict__ bk,
        const float* __restrict__ bv) {
    __shared__ float sm[SM_FLOATS];
    const int N = DM, K = DM;
    int sel = blockIdx.x >> 4;
    int hh  = blockIdx.x & 15;
    const float* Bhp  = (sel==0) ? g_wq_h : (sel==1) ? g_wk_h : g_wv_h;
    const float* Blp  = (sel==0) ? g_wq_l : (sel==1) ? g_wk_l : g_wv_l;
    const float* bias = (sel==0) ? bq : (sel==1) ? bk : bv;
    float* C          = (sel==0) ? g_q : (sel==1) ? g_k : g_v;

    int tid = threadIdx.x, lane = tid & 31, wid = tid >> 5;
    int wm = (wid & 3) * 32, wn = (wid >> 2) * 32;
    int aRow = tid >> 2, aCol = (tid & 3) << 2;
    int bRow = tid >> 4, bCol = (tid & 15) << 2;
    Ahp += (size_t)(blockIdx.y * 128) * K;
    Alp += (size_t)(blockIdx.y * 128) * K;
    Bhp += (size_t)hh * 64;
    Blp += (size_t)hh * 64;
    float acc[2][4][4] = {};

    MMA_MAINLOOP()

    int mBase = blockIdx.y*128 + wm + (lane>>2);
    int d0    = wn + ((lane&3)<<1);     // column within this head (0..63)
    #pragma unroll
    for (int mt = 0; mt < 2; mt++) {
        #pragma unroll
        for (int nt = 0; nt < 4; nt++) {
            int d = d0 + nt*8;
            float bv0 = bias[hh*64 + d], bv1 = bias[hh*64 + d + 1];
            #pragma unroll
            for (int half = 0; half < 2; half++) {
                int m = mBase + mt*16 + half*8;
                int b = m >> 10, s = m & 1023;
                float* crow = C + (size_t)(((b*NH + hh)*SS) + s)*HD + d;
                crow[0] = acc[mt][nt][half*2+0] + bv0;
                crow[1] = acc[mt][nt][half*2+1] + bv1;
            }
        }
    }
}

// ---------------- weight split (elementwise, no transpose) ----------------
__global__ __launch_bounds__(256) void k_wsplit(const float* __restrict__ W,
        float* __restrict__ Th, float* __restrict__ Tl, int n4) {
    int i = blockIdx.x*256 + threadIdx.x;
    if (i >= n4) return;
    float4 w = *(const float4*)(W + (size_t)i*4);
    float4 h, l;
    split2(w.x, h.x, l.x); split2(w.y, h.y, l.y);
    split2(w.z, h.z, l.z); split2(w.w, h.w, l.w);
    *(float4*)(Th + (size_t)i*4) = h;
    *(float4*)(Tl + (size_t)i*4) = l;
}

// ---------------- small kernels ----------------
__global__ void k_reset() { g_cnt[0]=0; g_cnt[1]=0; g_cnt[2]=0; }

__global__ __launch_bounds__(256) void k_embed(const int* __restrict__ x,
                                               const float* __restrict__ emb) {
    int row = blockIdx.x;
    int tok = x[row];
    int s   = row & (SS-1);
    const float* e = emb + (size_t)tok * DM;
    for (int d = threadIdx.x; d < DM; d += 256) {
        int p = d >> 1;
        float freq = expf((float)(2*p) * (-9.210340371976184f / 1024.f));
        float ang  = (float)s * freq;
        float pe   = (d & 1) ? cosf(ang) : sinf(ang);
        float v = e[d] * 32.f + pe;
        g_h[row*DM + d] = v;
        float h, l; split2(v, h, l);
        g_hh[row*DM + d] = h; g_hl[row*DM + d] = l;
    }
}

__global__ __launch_bounds__(256) void k_argmax(const float* __restrict__ W2,
                                                const float* __restrict__ b2) {
    int row  = blockIdx.x*8 + (threadIdx.x >> 5);
    int lane = threadIdx.x & 31;
    const float* r = g_rh + (size_t)row*RH;
    float s0 = 0.f, s1 = 0.f, s2 = 0.f;
    #pragma unroll
    for (int j = lane; j < RH; j += 32) {
        float v = r[j];
        s0 += v*W2[j*3+0]; s1 += v*W2[j*3+1]; s2 += v*W2[j*3+2];
    }
    #pragma unroll
    for (int o = 16; o; o >>= 1) {
        s0 += __shfl_xor_sync(0xffffffffu, s0, o);
        s1 += __shfl_xor_sync(0xffffffffu, s1, o);
        s2 += __shfl_xor_sync(0xffffffffu, s2, o);
    }
    if (lane == 0) {
        s0 += b2[0]; s1 += b2[1]; s2 += b2[2];
        int a = 0; float best = s0;
        if (s1 > best) { best = s1; a = 1; }
        if (s2 > best) { a = 2; }
        g_skip[row] = (a == 0);
        atomicAdd(&g_cnt[a], 1);
    }
}

// ---------------- attention (fp32 SIMT) ----------------
__global__ __launch_bounds__(256) void k_scores() {
    int z = blockIdx.z;
    int row0 = blockIdx.y*64, col0 = blockIdx.x*64;
    if (col0 > row0 + 63) return;
    const float* Q  = g_q + (size_t)z*SS*HD;
    const float* Kp = g_k + (size_t)z*SS*HD;
    float* out = g_scores + (size_t)z*SS*SS;
    __shared__ float Qs[16][64];
    __shared__ float Ks[16][64];
    int tid = threadIdx.x;
    int lr = tid >> 2, lc = (tid & 3) << 2;
    int tr = tid >> 4, tc = tid & 15;
    float acc[4][4] = {};
    for (int kk = 0; kk < HD; kk += 16) {
        float4 q4 = *reinterpret_cast<const float4*>(Q  + (size_t)(row0+lr)*HD + kk + lc);
        Qs[lc+0][lr]=q4.x; Qs[lc+1][lr]=q4.y; Qs[lc+2][lr]=q4.z; Qs[lc+3][lr]=q4.w;
        float4 k4 = *reinterpret_cast<const float4*>(Kp + (size_t)(col0+lr)*HD + kk + lc);
        Ks[lc+0][lr]=k4.x; Ks[lc+1][lr]=k4.y; Ks[lc+2][lr]=k4.z; Ks[lc+3][lr]=k4.w;
        __syncthreads();
        #pragma unroll
        for (int k2 = 0; k2 < 16; k2++) {
            float ra[4], rb[4];
            *reinterpret_cast<float4*>(ra) = *reinterpret_cast<const float4*>(&Qs[k2][tr*4]);
            *reinterpret_cast<float4*>(rb) = *reinterpret_cast<const float4*>(&Ks[k2][tc*4]);
            #pragma unroll
            for (int i=0;i<4;i++) {
                #pragma unroll
                for (int j=0;j<4;j++) acc[i][j] += ra[i]*rb[j];
            }
        }
        __syncthreads();
    }
    #pragma unroll
    for (int i=0;i<4;i++) {
        #pragma unroll
        for (int j=0;j<4;j++)
            out[(size_t)(row0 + tr*4 + i)*SS + col0 + tc*4 + j] = acc[i][j]*0.125f;
    }
}

__global__ __launch_bounds__(256) void k_softmax() {
    int r = blockIdx.x;
    int L = (r & (SS-1)) + 1;
    float* row = g_scores + (size_t)r*SS;
    __shared__ float buf[SS];
    __shared__ float red[8];
    int tid = threadIdx.x;
    float mx = -INFINITY;
    for (int c = tid; c < L; c += 256) { float v = row[c]; buf[c] = v; mx = fmaxf(mx, v); }
    for (int o=16;o;o>>=1) mx = fmaxf(mx, __shfl_xor_sync(0xffffffffu, mx, o));
    if ((tid&31)==0) red[tid>>5] = mx;
    __syncthreads();
    mx = red[0];
    #pragma unroll
    for (int i=1;i<8;i++) mx = fmaxf(mx, red[i]);
    float s = 0.f;
    for (int c = tid; c < L; c += 256) { float e = expf(buf[c]-mx); buf[c]=e; s += e; }
    __syncthreads();
    for (int o=16;o;o>>=1) s += __shfl_xor_sync(0xffffffffu, s, o);
    if ((tid&31)==0) red[tid>>5] = s;
    __syncthreads();
    s = red[0];
    #pragma unroll
    for (int i=1;i<8;i++) s += red[i];
    for (int c = tid; c < SS; c += 256) row[c] = (c < L) ? buf[c]/s : 0.f;
}

__global__ __launch_bounds__(256) void k_pv() {
    int z = blockIdx.z;
    int row0 = blockIdx.x*64;
    const float* P = g_scores + (size_t)z*SS*SS;
    const float* V = g_v      + (size_t)z*SS*HD;
    __shared__ float Ps[16][64];
    __shared__ float Vs[16][64];
    int tid = threadIdx.x;
    int pr = tid >> 2, pc = (tid & 3) << 2;
    int vr = tid >> 4, vc = (tid & 15) << 2;
    int tr = tid >> 4, tc = tid & 15;
    float acc[4][4] = {};
    int kmax = row0 + 64;
    for (int kk = 0; kk < kmax; kk += 16) {
        float4 p4 = *reinterpret_cast<const float4*>(P + (size_t)(row0+pr)*SS + kk + pc);
        Ps[pc+0][pr]=p4.x; Ps[pc+1][pr]=p4.y; Ps[pc+2][pr]=p4.z; Ps[pc+3][pr]=p4.w;
        float4 v4 = *reinterpret_cast<const float4*>(V + (size_t)(kk+vr)*HD + vc);
        *reinterpret_cast<float4*>(&Vs[vr][vc]) = v4;
        __syncthreads();
        #pragma unroll
        for (int k2 = 0; k2 < 16; k2++) {
            float ra[4], rb[4];
            *reinterpret_cast<float4*>(ra) = *reinterpret_cast<const float4*>(&Ps[k2][tr*4]);
            *reinterpret_cast<float4*>(rb) = *reinterpret_cast<const float4*>(&Vs[k2][tc*4]);
            #pragma unroll
            for (int i=0;i<4;i++) {
                #pragma unroll
                for (int j=0;j<4;j++) acc[i][j] += ra[i]*rb[j];
            }
        }
        __syncthreads();
    }
    int b = z >> 4, hh = z & 15;
    #pragma unroll
    for (int i=0;i<4;i++) {
        #pragma unroll
        for (int j=0;j<4;j++) {
            size_t o = (size_t)(b*SS + row0 + tr*4 + i)*DM + hh*HD + tc*4 + j;
            float h, l; split2(acc[i][j], h, l);
            g_atth[o] = h; g_attl[o] = l;
        }
    }
}

// ---------------- LayerNorm variants ----------------
__global__ __launch_bounds__(256) void k_lnadd(const float* __restrict__ res,
        const float* __restrict__ x, const float* __restrict__ g,
        const float* __restrict__ b, float* __restrict__ o,
        float* __restrict__ oh, float* __restrict__ ol) {
    int row = blockIdx.x;
    const float* rp = res + (size_t)row*DM;
    const float* xp = x   + (size_t)row*DM;
    __shared__ float buf[DM];
    __shared__ float red[8];
    int tid = threadIdx.x;
    float s = 0.f;
    for (int d = tid; d < DM; d += 256) { float v = rp[d]+xp[d]; buf[d]=v; s += v; }
    for (int off=16;off;off>>=1) s += __shfl_xor_sync(0xffffffffu, s, off);
    if ((tid&31)==0) red[tid>>5] = s;
    __syncthreads();
    s = red[0];
    #pragma unroll
    for (int i=1;i<8;i++) s += red[i];
    float mu = s * (1.f/DM);
    float vs = 0.f;
    for (int d = tid; d < DM; d += 256) { float v = buf[d]-mu; vs += v*v; }
    __syncthreads();
    for (int off=16;off;off>>=1) vs += __shfl_xor_sync(0xffffffffu, vs, off);
    if ((tid&31)==0) red[tid>>5] = vs;
    __syncthreads();
    vs = red[0];
    #pragma unroll
    for (int i=1;i<8;i++) vs += red[i];
    float inv = rsqrtf(vs * (1.f/DM) + 1e-5f);
    for (int d = tid; d < DM; d += 256) {
        float v = (buf[d]-mu)*inv*g[d] + b[d];
        size_t idx = (size_t)row*DM + d;
        o[idx] = v;
        float h, l; split2(v, h, l);
        oh[idx] = h; ol[idx] = l;
    }
}

// LN2 fused with router select: skip rows keep old h (no write).
__global__ __launch_bounds__(256) void k_lnadd_sel(const float* __restrict__ res,
        const float* __restrict__ x, const float* __restrict__ g,
        const float* __restrict__ b, float* __restrict__ o,
        float* __restrict__ oh, float* __restrict__ ol) {
    int row = blockIdx.x;
    if (g_skip[row]) return;
    const float* rp = res + (size_t)row*DM;
    const float* xp = x   + (size_t)row*DM;
    __shared__ float buf[DM];
    __shared__ float red[8];
    int tid = threadIdx.x;
    float s = 0.f;
    for (int d = tid; d < DM; d += 256) { float v = rp[d]+xp[d]; buf[d]=v; s += v; }
    for (int off=16;off;off>>=1) s += __shfl_xor_sync(0xffffffffu, s, off);
    if ((tid&31)==0) red[tid>>5] = s;
    __syncthreads();
    s = red[0];
    #pragma unroll
    for (int i=1;i<8;i++) s += red[i];
    float mu = s * (1.f/DM);
    float vs = 0.f;
    for (int d = tid; d < DM; d += 256) { float v = buf[d]-mu; vs += v*v; }
    __syncthreads();
    for (int off=16;off;off>>=1) vs += __shfl_xor_sync(0xffffffffu, vs, off);
    if ((tid&31)==0) red[tid>>5] = vs;
    __syncthreads();
    vs = red[0];
    #pragma unroll
    for (int i=1;i<8;i++) vs += red[i];
    float inv = rsqrtf(vs * (1.f/DM) + 1e-5f);
    for (int d = tid; d < DM; d += 256) {
        float v = (buf[d]-mu)*inv*g[d] + b[d];
        size_t idx = (size_t)row*DM + d;
        o[idx] = v;
        float h, l; split2(v, h, l);
        oh[idx] = h; ol[idx] = l;
    }
}

__global__ void k_finalize(float* out, int base) {
    float sk = (float)g_cnt[0], fw = (float)g_cnt[1], rc = (float)g_cnt[2];
    float total = (float)(MM * NL);
    out[base+0] = (fw + rc) / (float)MM;
    out[base+1] = sk / total;
    out[base+2] = fw / total;
    out[base+3] = rc / total;
}

// ---------------- host driver ----------------
extern "C" void kernel_launch(void* const* d_in, const int* in_sizes, int n_in,
                              void* d_out, int out_size) {
    const int*   x    = (const int*)  d_in[0];
    const float* emb  = (const float*)d_in[1];
    const float* Wq   = (const float*)d_in[2],  *bq   = (const float*)d_in[3];
    const float* Wk   = (const float*)d_in[4],  *bk   = (const float*)d_in[5];
    const float* Wv   = (const float*)d_in[6],  *bv   = (const float*)d_in[7];
    const float* Wo   = (const float*)d_in[8],  *bo   = (const float*)d_in[9];
    const float* ln1g = (const float*)d_in[10], *ln1b = (const float*)d_in[11];
    const float* Wf1  = (const float*)d_in[12], *bf1  = (const float*)d_in[13];
    const float* Wf2  = (const float*)d_in[14], *bf2  = (const float*)d_in[15];
    const float* ln2g = (const float*)d_in[16], *ln2b = (const float*)d_in[17];
    const float* rW1  = (const float*)d_in[18], *rb1  = (const float*)d_in[19];
    const float* rW2  = (const float*)d_in[20], *rb2  = (const float*)d_in[21];
    const float* Wout = (const float*)d_in[22], *bout = (const float*)d_in[23];
    float* out = (float*)d_out;

    float *h,*hh,*hl,*h1,*h1h,*h1l,*atth,*attl,*ffh,*ffl,*t2,*rh;
    cudaGetSymbolAddress((void**)&h,   g_h);   cudaGetSymbolAddress((void**)&hh,  g_hh);
    cudaGetSymbolAddress((void**)&hl,  g_hl);  cudaGetSymbolAddress((void**)&h1,  g_h1);
    cudaGetSymbolAddress((void**)&h1h, g_h1h); cudaGetSymbolAddress((void**)&h1l, g_h1l);
    cudaGetSymbolAddress((void**)&atth,g_atth);cudaGetSymbolAddress((void**)&attl,g_attl);
    cudaGetSymbolAddress((void**)&ffh, g_ffh); cudaGetSymbolAddress((void**)&ffl, g_ffl);
    cudaGetSymbolAddress((void**)&t2,  g_t2);  cudaGetSymbolAddress((void**)&rh,  g_rh);
    float *wqh,*wql,*wkh,*wkl,*wvh,*wvl,*woh,*wol,*f1h,*f1l,*f2h,*f2l,*wth,*wtl,*r1h,*r1l;
    cudaGetSymbolAddress((void**)&wqh, g_wq_h); cudaGetSymbolAddress((void**)&wql, g_wq_l);
    cudaGetSymbolAddress((void**)&wkh, g_wk_h); cudaGetSymbolAddress((void**)&wkl, g_wk_l);
    cudaGetSymbolAddress((void**)&wvh, g_wv_h); cudaGetSymbolAddress((void**)&wvl, g_wv_l);
    cudaGetSymbolAddress((void**)&woh, g_wo_h); cudaGetSymbolAddress((void**)&wol, g_wo_l);
    cudaGetSymbolAddress((void**)&f1h, g_wf1_h);cudaGetSymbolAddress((void**)&f1l, g_wf1_l);
    cudaGetSymbolAddress((void**)&f2h, g_wf2_h);cudaGetSymbolAddress((void**)&f2l, g_wf2_l);
    cudaGetSymbolAddress((void**)&wth, g_wout_h);cudaGetSymbolAddress((void**)&wtl, g_wout_l);
    cudaGetSymbolAddress((void**)&r1h, g_rw1_h);cudaGetSymbolAddress((void**)&r1l, g_rw1_l);

    // weight split (elementwise, ~70us total)
    k_wsplit<<<DM*DM/4/256, 256>>>(Wq, wqh, wql, DM*DM/4);
    k_wsplit<<<DM*DM/4/256, 256>>>(Wk, wkh, wkl, DM*DM/4);
    k_wsplit<<<DM*DM/4/256, 256>>>(Wv, wvh, wvl, DM*DM/4);
    k_wsplit<<<DM*DM/4/256, 256>>>(Wo, woh, wol, DM*DM/4);
    k_wsplit<<<FFD*DM/4/256, 256>>>(Wf1, f1h, f1l, FFD*DM/4);
    k_wsplit<<<FFD*DM/4/256, 256>>>(Wf2, f2h, f2l, FFD*DM/4);
    k_wsplit<<<(int)((size_t)VOC*DM/4/256), 256>>>(Wout, wth, wtl, (int)((size_t)VOC*DM/4));
    k_wsplit<<<NL*DM*RH/4/256, 256>>>(rW1, r1h, r1l, NL*DM*RH/4);

    k_reset<<<1,1>>>();
    k_embed<<<MM,256>>>(x, emb);

    dim3 gdd (DM/64,  MM/128);      // 16 x 16
    dim3 gqkv(48,     MM/128);
    dim3 gff1(FFD/64, MM/128);      // 64 x 16
    dim3 grt (RH/64,  MM/128);      // 2 x 16
    dim3 gsc (16, 16, NZ);
    dim3 gpv (16, 1,  NZ);

    for (int i = 0; i < NL; i++) {
        k_gemm<1><<<grt, 256>>>(hh, hl, r1h + (size_t)i*DM*RH, r1l + (size_t)i*DM*RH,
                                rb1 + (size_t)i*RH, rh, nullptr, RH, DM);
        k_argmax<<<MM/8,256>>>(rW2 + (size_t)i*RH*3, rb2 + (size_t)i*3);
        k_gemm_qkv<<<gqkv, 256>>>(hh, hl, bq, bk, bv);
        k_scores<<<gsc,256>>>();
        k_softmax<<<NZ*SS,256>>>();
        k_pv<<<gpv,256>>>();
        k_gemm<0><<<gdd, 256>>>(atth, attl, woh, wol, bo, t2, nullptr, DM, DM);
        k_lnadd<<<MM,256>>>(h, t2, ln1g, ln1b, h1, h1h, h1l);
        k_gemm<2><<<gff1, 256>>>(h1h, h1l, f1h, f1l, bf1, ffh, ffl, FFD, DM);
        k_gemm<0><<<gdd, 256>>>(ffh, ffl, f2h, f2l, bf2, t2, nullptr, DM, FFD);
        k_lnadd_sel<<<MM,256>>>(h1, t2, ln2g, ln2b, h, hh, hl);
    }
    k_gemm<0><<<dim3(VOC/64, MM/128), 256>>>(hh, hl, wth, wtl, bout, out, nullptr, VOC, DM);
    k_finalize<<<1,1>>>(out, out_size - 4);
}